// round 8
// baseline (speedup 1.0000x reference)
#include <cuda_runtime.h>

// Problem constants
#define HB   4
#define CDIM 64
#define C2   256
#define HFD  128
#define HH   256
#define WW   256

// ---------------------------------------------------------------------------
// Scratch (device globals: allocation-free rule)
// ---------------------------------------------------------------------------
__device__ float g_hmid[HB * C2 * HH * WW];   // 256 MiB intermediate
__device__ float g_krev[64 * C2 * 2];         // tap pairs: [r*8+m][c] = (k[r][m], k[r][(m-1)&7])
__device__ float g_wt[64 * C2];               // W_in transposed: [d][c]

// ---------------------------------------------------------------------------
// f32x2 packed helpers
// ---------------------------------------------------------------------------
__device__ __forceinline__ unsigned long long pk2(float lo, float hi) {
    unsigned long long r;
    asm("mov.b64 %0, {%1,%2};" : "=l"(r) : "f"(lo), "f"(hi));
    return r;
}
__device__ __forceinline__ void upk2(unsigned long long v, float& lo, float& hi) {
    asm("mov.b64 {%0,%1}, %2;" : "=f"(lo), "=f"(hi) : "l"(v));
}
__device__ __forceinline__ unsigned long long ffma2(unsigned long long a,
                                                    unsigned long long b,
                                                    unsigned long long c) {
    unsigned long long d;
    asm("fma.rn.f32x2 %0, %1, %2, %3;" : "=l"(d) : "l"(a), "l"(b), "l"(c));
    return d;
}

// ---------------------------------------------------------------------------
// cp.async helpers (8B, zero-fill when invalid)
// ---------------------------------------------------------------------------
__device__ __forceinline__ void cp8(void* dst, const void* src, bool valid) {
    unsigned u = (unsigned)__cvta_generic_to_shared(dst);
    int sz = valid ? 8 : 0;
    asm volatile("cp.async.ca.shared.global [%0], [%1], 8, %2;\n"
                 :: "r"(u), "l"(src), "r"(sz));
}
__device__ __forceinline__ void cp_commit() {
    asm volatile("cp.async.commit_group;\n");
}
__device__ __forceinline__ void cp_wait3() {
    asm volatile("cp.async.wait_group 3;\n");
}

// ---------------------------------------------------------------------------
// K0: taps k_c = irfft2(F_c); emit reversed-adjacent packed pairs + W_in^T.
// ---------------------------------------------------------------------------
__global__ void k_prep(const float* __restrict__ filt, const float* __restrict__ w_in) {
    const int c = threadIdx.x;
    const float R2 = 0.70710678118654752f;
    const float CT[8] = {1.f,  R2, 0.f, -R2, -1.f, -R2,  0.f,  R2};
    const float ST[8] = {0.f,  R2, 1.f,  R2,  0.f, -R2, -1.f, -R2};

    float F[8][5];
    #pragma unroll
    for (int u = 0; u < 8; ++u)
        #pragma unroll
        for (int v = 0; v < 5; ++v)
            F[u][v] = filt[c * 40 + u * 5 + v];

    float kv[64];
    #pragma unroll
    for (int p = 0; p < 8; ++p) {
        float gr[5], gi[5];
        #pragma unroll
        for (int v = 0; v < 5; ++v) { gr[v] = 0.f; gi[v] = 0.f; }
        #pragma unroll
        for (int u = 0; u < 8; ++u) {
            float cc = CT[(u * p) & 7], ss = ST[(u * p) & 7];
            #pragma unroll
            for (int v = 0; v < 5; ++v) {
                gr[v] = fmaf(F[u][v], cc, gr[v]);
                gi[v] = fmaf(F[u][v], ss, gi[v]);
            }
        }
        #pragma unroll
        for (int q = 0; q < 8; ++q) {
            float val = gr[0] + ((q & 1) ? -gr[4] : gr[4]);
            #pragma unroll
            for (int v = 1; v <= 3; ++v)
                val += 2.f * (gr[v] * CT[(v * q) & 7] - gi[v] * ST[(v * q) & 7]);
            kv[p * 8 + q] = val * (1.f / 64.f);
        }
    }
    #pragma unroll
    for (int r = 0; r < 8; ++r)
        #pragma unroll
        for (int m = 0; m < 8; ++m) {
            int base = 2 * ((r * 8 + m) * C2 + c);
            g_krev[base]     = kv[r * 8 + m];
            g_krev[base + 1] = kv[r * 8 + ((m - 1) & 7)];
        }
    for (int d = 0; d < 64; ++d)
        g_wt[d * C2 + c] = w_in[c * 64 + d];
}

// ---------------------------------------------------------------------------
// K1: per-patch fused  h = W_in x  +  8x8 circular conv.
// Conv packed over v-pairs: acc pair = (even-v partial, odd-v partial);
// h2 stays packed from projection (no broadcast movs); tap rows double-buffered.
// smem: sx [64][64] (16KB) + syc chunk [16][257] (16.4KB)
// ---------------------------------------------------------------------------
#define K1_SMEM ((64 * 64 + 16 * 257) * 4)

__global__ __launch_bounds__(256) void k_proj_spec(const float* __restrict__ x) {
    extern __shared__ float smem[];
    float* sx  = smem;               // [d][px]
    float* syc = smem + 64 * 64;     // [16][257] output chunk stage

    const int t  = threadIdx.x;
    const int pi = blockIdx.x;
    const int b  = pi >> 10;
    const int rr = pi & 1023;
    const int pr = rr >> 5, pc = rr & 31;
    const int c  = t;

    // stage x patch (64 in-channels x 64 px)
    {
        int xbase = b * (CDIM * HH * WW) + (pr * 8) * WW + pc * 8;
        for (int k = 0; k < 16; ++k) {
            int e  = t + k * 256;
            int dd = e >> 6, px = e & 63;
            sx[e] = x[xbase + dd * (HH * WW) + (px >> 3) * WW + (px & 7)];
        }
    }
    __syncthreads();

    // Projection: h2[u*4+j] = (h[u][2j], h[u][2j+1]), 32 packed accumulators
    unsigned long long h2[32];
    #pragma unroll
    for (int j = 0; j < 32; ++j) h2[j] = 0ULL;
    {
        const unsigned long long* sx2 = reinterpret_cast<const unsigned long long*>(sx);
        for (int d = 0; d < 64; ++d) {
            float w = g_wt[d * C2 + c];              // coalesced, L1-resident
            unsigned long long w2 = pk2(w, w);
            #pragma unroll
            for (int j = 0; j < 32; ++j)
                h2[j] = ffma2(w2, sx2[d * 32 + j], h2[j]);
        }
    }

    const unsigned long long* gk =
        reinterpret_cast<const unsigned long long*>(g_krev);  // [64][256]
    int obase = b * (C2 * HH * WW) + (pr * 8) * WW + pc * 8;

    // Conv: y[p][q] = sum_u sum_vpair pairdot(h2[u][j], krev[(p-u)&7][(q-2j)&7])
    #pragma unroll
    for (int half = 0; half < 2; ++half) {
        unsigned long long acc2[32];
        #pragma unroll
        for (int i = 0; i < 32; ++i) acc2[i] = 0ULL;

        unsigned long long ktA[8], ktB[8];
        #pragma unroll
        for (int m = 0; m < 8; ++m) ktA[m] = gk[m * C2 + c];

        #pragma unroll
        for (int r = 0; r < 8; ++r) {
            const unsigned long long* cur = (r & 1) ? ktB : ktA;
            if (r < 7) {
                unsigned long long* nxt = (r & 1) ? ktA : ktB;
                #pragma unroll
                for (int m = 0; m < 8; ++m)
                    nxt[m] = gk[((r + 1) * 8 + m) * C2 + c];
            }
            #pragma unroll
            for (int pl = 0; pl < 4; ++pl) {
                int p = half * 4 + pl;
                int u = (p - r) & 7;
                #pragma unroll
                for (int q = 0; q < 8; ++q)
                    #pragma unroll
                    for (int vp = 0; vp < 4; ++vp)
                        acc2[pl * 8 + q] = ffma2(h2[u * 4 + vp],
                                                 cur[(q - 2 * vp) & 7],
                                                 acc2[pl * 8 + q]);
            }
        }

        // epilogue: two 16-px chunks, staged transpose, coalesced store
        #pragma unroll
        for (int ch2 = 0; ch2 < 2; ++ch2) {
            #pragma unroll
            for (int pl2 = 0; pl2 < 2; ++pl2) {
                int pl = ch2 * 2 + pl2;
                #pragma unroll
                for (int q = 0; q < 8; ++q) {
                    float lo, hi;
                    upk2(acc2[pl * 8 + q], lo, hi);
                    syc[(pl2 * 8 + q) * 257 + c] = lo + hi;
                }
            }
            __syncthreads();
            int pxb = half * 32 + ch2 * 16;
            for (int k = 0; k < 16; ++k) {
                int e   = t + k * 256;
                int cc  = e >> 4, pxl = e & 15;
                int px  = pxb + pxl;
                g_hmid[obase + cc * (HH * WW) + (px >> 3) * WW + (px & 7)] =
                    syc[pxl * 257 + cc];
            }
            __syncthreads();
        }
    }
}

// ---------------------------------------------------------------------------
// K2: depthwise 3x3 + exact GELU gate + W_out, cp.async 5-stage ring.
// Tile per stage: 2 channels x 18 rows x 20 cols (8B chunks, zfill halo).
// ---------------------------------------------------------------------------
#define K2_TILEF  10496                       // float offset of tile ring
#define K2_SMEM   ((K2_TILEF + 5 * 1440) * 4) // 70784 B

__device__ __forceinline__ void k2_issue(float* smemf, int s, int ch,
                                         int b, int y0, int x0, int t) {
    unsigned long long* stg =
        reinterpret_cast<unsigned long long*>(smemf + K2_TILEF + s * 1440);
    #pragma unroll
    for (int k = 0; k < 3; ++k) {
        int i = t + k * 256;
        if (i < 720) {
            int which = (i >= 360) ? 1 : 0;
            int j   = i - which * 360;
            int row = j / 10, u = j - row * 10;
            int gy  = y0 - 1 + row;
            int gx0 = x0 - 2 + 2 * u;
            bool ok = (gy >= 0) & (gy < 256) & (gx0 >= 0) & (gx0 <= 254);
            const float* src = g_hmid +
                (((b * C2 + ch + which * 128) << 16) + (ok ? gy * 256 + gx0 : 0));
            cp8(stg + i, src, ok);
        }
    }
}

__global__ __launch_bounds__(256, 2) void k_dw_out(const float* __restrict__ w_dw,
                                                   const float* __restrict__ w_out,
                                                   float* __restrict__ out) {
    extern __shared__ float smem[];
    float* swo  = smem;              // [c][o] w_out^T  (8192 floats)
    float* sdw  = smem + 8192;       // [256*9]         (2304 floats)
    float* sout = smem;              // ALIAS (out phase): [px][o], stride 65

    const int t  = threadIdx.x;
    const int b  = blockIdx.z;
    const int x0 = blockIdx.x * 16, y0 = blockIdx.y * 16;
    const int yl = t >> 4, xl = t & 15;

    for (int k = 0; k < 32; ++k) {
        int e = t + k * 256;
        int o = e >> 7, cc = e & 127;
        swo[cc * 64 + o] = w_out[e];
    }
    for (int e = t; e < 2304; e += 256) sdw[e] = w_dw[e];

    // prologue: 4 stages in flight
    #pragma unroll
    for (int s = 0; s < 4; ++s) { k2_issue(smem, s, s, b, y0, x0, t); cp_commit(); }

    unsigned long long acc2[32];
    #pragma unroll
    for (int j = 0; j < 32; ++j) acc2[j] = 0ULL;

    for (int c = 0; c < 128; ++c) {
        cp_wait3();
        __syncthreads();     // stage c visible to all; stage (c-1) reads done
        if (c + 4 < 128) k2_issue(smem, (c + 4) % 5, c + 4, b, y0, x0, t);
        cp_commit();

        const float* stg = smem + K2_TILEF + (c % 5) * 1440;
        const float* wd1 = sdw + c * 9;
        const float* wd2 = sdw + (c + 128) * 9;
        float d1 = 0.f, d2 = 0.f;
        #pragma unroll
        for (int i = 0; i < 3; ++i)
            #pragma unroll
            for (int j = 0; j < 3; ++j) {
                int o = (yl + i) * 20 + xl + 1 + j;
                d1 = fmaf(stg[o],       wd1[i * 3 + j], d1);
                d2 = fmaf(stg[720 + o], wd2[i * 3 + j], d2);
            }
        float g = 0.5f * d1 * (1.f + erff(d1 * 0.70710678118654752f)) * d2;
        unsigned long long gg = pk2(g, g);
        const unsigned long long* wrow =
            reinterpret_cast<const unsigned long long*>(swo + c * 64);
        #pragma unroll
        for (int j = 0; j < 32; ++j)
            acc2[j] = ffma2(wrow[j], gg, acc2[j]);
    }

    __syncthreads();   // last stage reads done before sout aliases tiles/weights
    #pragma unroll
    for (int j = 0; j < 32; ++j) {
        float lo, hi;
        upk2(acc2[j], lo, hi);
        sout[t * 65 + 2 * j]     = lo;
        sout[t * 65 + 2 * j + 1] = hi;
    }
    __syncthreads();
    for (int k = 0; k < 64; ++k) {
        int e  = t + k * 256;
        int o  = e >> 8, px = e & 255;
        int oy = px >> 4, ox = px & 15;
        out[((b * 64 + o) << 16) + (y0 + oy) * 256 + x0 + ox] = sout[px * 65 + o];
    }
}

// ---------------------------------------------------------------------------
// launch
// ---------------------------------------------------------------------------
extern "C" void kernel_launch(void* const* d_in, const int* in_sizes, int n_in,
                              void* d_out, int out_size) {
    const float* x     = (const float*)d_in[0];   // (4,64,256,256)
    const float* w_in  = (const float*)d_in[1];   // (256,64)
    const float* w_dw  = (const float*)d_in[2];   // (256,1,3,3)
    const float* filt  = (const float*)d_in[3];   // (256,1,1,8,5)
    const float* w_out = (const float*)d_in[4];   // (64,128)
    float* out = (float*)d_out;                   // (4,64,256,256)

    cudaFuncSetAttribute(k_proj_spec, cudaFuncAttributeMaxDynamicSharedMemorySize, K1_SMEM);
    cudaFuncSetAttribute(k_dw_out,    cudaFuncAttributeMaxDynamicSharedMemorySize, K2_SMEM);

    k_prep<<<1, 256>>>(filt, w_in);
    k_proj_spec<<<HB * 32 * 32, 256, K1_SMEM>>>(x);
    k_dw_out<<<dim3(16, 16, HB), 256, K2_SMEM>>>(w_dw, w_out, out);
}

// round 11
// speedup vs baseline: 1.2469x; 1.2469x over previous
#include <cuda_runtime.h>

// Problem constants
#define HB   4
#define CDIM 64
#define C2   256
#define HFD  128
#define HH   256
#define WW   256

// ---------------------------------------------------------------------------
// Scratch (device globals: allocation-free rule)
// ---------------------------------------------------------------------------
__device__ float g_hmid[HB * C2 * HH * WW];   // 256 MiB intermediate
__device__ float g_krev[64 * C2 * 2];         // tap pairs: [r*8+m][c] = (k[r][m], k[r][(m-1)&7])

// ---------------------------------------------------------------------------
// f32x2 packed helpers (Blackwell FFMA2: 2x fp32 throughput)
// ---------------------------------------------------------------------------
__device__ __forceinline__ unsigned long long pk2(float lo, float hi) {
    unsigned long long r;
    asm("mov.b64 %0, {%1,%2};" : "=l"(r) : "f"(lo), "f"(hi));
    return r;
}
__device__ __forceinline__ void upk2(unsigned long long v, float& lo, float& hi) {
    asm("mov.b64 {%0,%1}, %2;" : "=f"(lo), "=f"(hi) : "l"(v));
}
__device__ __forceinline__ unsigned long long ffma2(unsigned long long a,
                                                    unsigned long long b,
                                                    unsigned long long c) {
    unsigned long long d;
    asm("fma.rn.f32x2 %0, %1, %2, %3;" : "=l"(d) : "l"(a), "l"(b), "l"(c));
    return d;
}

// ---------------------------------------------------------------------------
// K0: taps k_c = irfft2(F_c) (8x5 real spectrum -> 8x8 taps);
// emit reversed-adjacent packed pairs for the v-pair conv.
// ---------------------------------------------------------------------------
__global__ void k_prep(const float* __restrict__ filt) {
    const int c = threadIdx.x;
    const float R2 = 0.70710678118654752f;
    const float CT[8] = {1.f,  R2, 0.f, -R2, -1.f, -R2,  0.f,  R2};
    const float ST[8] = {0.f,  R2, 1.f,  R2,  0.f, -R2, -1.f, -R2};

    float F[8][5];
    #pragma unroll
    for (int u = 0; u < 8; ++u)
        #pragma unroll
        for (int v = 0; v < 5; ++v)
            F[u][v] = filt[c * 40 + u * 5 + v];

    float kv[64];
    #pragma unroll
    for (int p = 0; p < 8; ++p) {
        float gr[5], gi[5];
        #pragma unroll
        for (int v = 0; v < 5; ++v) { gr[v] = 0.f; gi[v] = 0.f; }
        #pragma unroll
        for (int u = 0; u < 8; ++u) {
            float cc = CT[(u * p) & 7], ss = ST[(u * p) & 7];
            #pragma unroll
            for (int v = 0; v < 5; ++v) {
                gr[v] = fmaf(F[u][v], cc, gr[v]);
                gi[v] = fmaf(F[u][v], ss, gi[v]);
            }
        }
        #pragma unroll
        for (int q = 0; q < 8; ++q) {
            float val = gr[0] + ((q & 1) ? -gr[4] : gr[4]);
            #pragma unroll
            for (int v = 1; v <= 3; ++v)
                val += 2.f * (gr[v] * CT[(v * q) & 7] - gi[v] * ST[(v * q) & 7]);
            kv[p * 8 + q] = val * (1.f / 64.f);
        }
    }
    #pragma unroll
    for (int r = 0; r < 8; ++r)
        #pragma unroll
        for (int m = 0; m < 8; ++m) {
            int base = 2 * ((r * 8 + m) * C2 + c);
            g_krev[base]     = kv[r * 8 + m];
            g_krev[base + 1] = kv[r * 8 + ((m - 1) & 7)];
        }
}

// ---------------------------------------------------------------------------
// K1: per-patch fused  h = W_in x (f32x2)  +  8x8 circular conv (v-pair form).
// One block = one 8x8 patch; thread c owns channel c in registers.
// Conv uses packed h2 directly (no broadcast movs); taps streamed from L2
// row-by-row (double-buffered) -> ~175 live regs, no spills.
// smem: phase1 [64][257] W_in^T | [64][64] x   -> aliased -> phase2 [64][257] y
// ---------------------------------------------------------------------------
#define K1_SMEM ((64 * 257 + 64 * 64) * 4)

__global__ __launch_bounds__(256) void k_proj_spec(const float* __restrict__ x,
                                                   const float* __restrict__ w_in) {
    extern __shared__ float smem[];
    float* sw  = smem;               // [d][c], stride 257
    float* sx  = sw + 64 * 257;      // [d][px]
    float* syb = smem;               // ALIAS: [px][c], stride 257 (after sync)

    const int t  = threadIdx.x;
    const int pi = blockIdx.x;
    const int b  = pi >> 10;
    const int rr = pi & 1023;
    const int pr = rr >> 5, pc = rr & 31;
    const int c  = t;

    // stage W_in transposed ([c][d] global -> [d][c] smem)
    for (int k = 0; k < 64; ++k) {
        int e  = t + k * 256;
        int cc = e >> 6, dd = e & 63;
        sw[dd * 257 + cc] = w_in[e];
    }
    // stage x patch (64 input channels x 64 px)
    {
        int xbase = b * (CDIM * HH * WW) + (pr * 8) * WW + pc * 8;
        for (int k = 0; k < 16; ++k) {
            int e  = t + k * 256;
            int dd = e >> 6, px = e & 63;
            sx[e] = x[xbase + dd * (HH * WW) + (px >> 3) * WW + (px & 7)];
        }
    }
    __syncthreads();

    // Projection: h2[u*4+j] = (h[u][2j], h[u][2j+1]) -- 32 packed accumulators
    unsigned long long h2[32];
    #pragma unroll
    for (int j = 0; j < 32; ++j) h2[j] = 0ULL;
    {
        const unsigned long long* sx2 =
            reinterpret_cast<const unsigned long long*>(sx);
        for (int d = 0; d < 64; ++d) {
            float w = sw[d * 257 + c];
            unsigned long long w2 = pk2(w, w);
            #pragma unroll
            for (int j = 0; j < 32; ++j)
                h2[j] = ffma2(w2, sx2[d * 32 + j], h2[j]);
        }
    }

    __syncthreads();   // all reads of sw/sx done before syb (alias) writes

    const unsigned long long* gk =
        reinterpret_cast<const unsigned long long*>(g_krev);  // [64 rows][256 c]

    // Conv, v-pair form, two half-passes over p (acc pairs = (even-v, odd-v)):
    //   pair(p,q) += h2[u][j] * krev[(p-u)&7][(q-2j)&7],  y = lo + hi
    #pragma unroll
    for (int half = 0; half < 2; ++half) {
        unsigned long long acc2[32];            // [pl][q], pl = p - half*4
        #pragma unroll
        for (int i = 0; i < 32; ++i) acc2[i] = 0ULL;

        unsigned long long ktA[8], ktB[8];      // tap-row double buffer
        #pragma unroll
        for (int m = 0; m < 8; ++m) ktA[m] = gk[m * C2 + c];

        #pragma unroll
        for (int r = 0; r < 8; ++r) {
            const unsigned long long* cur = (r & 1) ? ktB : ktA;
            if (r < 7) {
                unsigned long long* nxt = (r & 1) ? ktA : ktB;
                #pragma unroll
                for (int m = 0; m < 8; ++m)
                    nxt[m] = gk[((r + 1) * 8 + m) * C2 + c];
            }
            #pragma unroll
            for (int pl = 0; pl < 4; ++pl) {
                int u = ((half * 4 + pl) - r) & 7;
                #pragma unroll
                for (int q = 0; q < 8; ++q)
                    #pragma unroll
                    for (int vp = 0; vp < 4; ++vp)
                        acc2[pl * 8 + q] = ffma2(h2[u * 4 + vp],
                                                 cur[(q - 2 * vp) & 7],
                                                 acc2[pl * 8 + q]);
            }
        }
        #pragma unroll
        for (int pl = 0; pl < 4; ++pl)
            #pragma unroll
            for (int q = 0; q < 8; ++q) {
                float lo, hi;
                upk2(acc2[pl * 8 + q], lo, hi);
                syb[((half * 4 + pl) * 8 + q) * 257 + c] = lo + hi;
            }
    }
    __syncthreads();

    // cooperative coalesced store
    int obase = b * (C2 * HH * WW) + (pr * 8) * WW + pc * 8;
    for (int k = 0; k < 64; ++k) {
        int e  = t + k * 256;
        int cc = e >> 6, px = e & 63;
        g_hmid[obase + cc * (HH * WW) + (px >> 3) * WW + (px & 7)] =
            syb[px * 257 + cc];
    }
}

// ---------------------------------------------------------------------------
// K2: depthwise 3x3 (SAME) + exact GELU gate + W_out projection.
// (VERBATIM round-5 version: software-pipelined channel loop, ping-pong smem
// tiles, register prefetch 2 channels ahead, 1 barrier/iter, 2 blocks/SM.)
// ---------------------------------------------------------------------------
#define K2_SMEM (16640 * 4)   // max(loop phase 12048, out phase 16640) floats

__device__ __forceinline__ void k2_prefetch(int b, int c, int y0, int x0, int t,
                                            float r[3]) {
    #pragma unroll
    for (int s = 0; s < 3; ++s) {
        int i = t + s * 256;
        float v = 0.f;
        if (i < 648) {
            int which = (i >= 324) ? 1 : 0;
            int j  = i - which * 324;
            int rr = j / 18, cc = j - rr * 18;
            int gy = y0 - 1 + rr, gx = x0 - 1 + cc;
            if (gy >= 0 && gy < 256 && gx >= 0 && gx < 256)
                v = g_hmid[((b * C2 + c + which * 128) << 16) + gy * 256 + gx];
        }
        r[s] = v;
    }
}

__global__ __launch_bounds__(256, 2) void k_dw_out(const float* __restrict__ w_dw,
                                                   const float* __restrict__ w_out,
                                                   float* __restrict__ out) {
    extern __shared__ float smem[];
    float* swo   = smem;              // [c][o] w_out^T, stride 66     (8448)
    float* sdw   = smem + 8448;       // [256*9] depthwise weights     (2304)
    float* tiles = smem + 10752;      // 2 buffers x (2ch x 324)       (1296)
    float* sout  = smem;              // ALIAS (out phase): [px][o], stride 65

    const int t  = threadIdx.x;
    const int b  = blockIdx.z;
    const int x0 = blockIdx.x * 16, y0 = blockIdx.y * 16;
    const int yl = t >> 4, xl = t & 15;

    for (int k = 0; k < 32; ++k) {
        int e = t + k * 256;
        int o = e >> 7, cc = e & 127;
        swo[cc * 66 + o] = w_out[e];
    }
    for (int e = t; e < 2304; e += 256) sdw[e] = w_dw[e];

    // prefetch channel 0 -> buf0, channel 1 -> registers
    float rA[3], rN[3];
    k2_prefetch(b, 0, y0, x0, t, rA);
    #pragma unroll
    for (int s = 0; s < 3; ++s) {
        int i = t + s * 256;
        if (i < 648) tiles[i] = rA[s];
    }
    k2_prefetch(b, 1, y0, x0, t, rA);   // rA now holds c=1 data
    __syncthreads();

    unsigned long long acc2[32];
    #pragma unroll
    for (int j = 0; j < 32; ++j) acc2[j] = 0ULL;

    for (int c = 0; c < 128; ++c) {
        float* cur = tiles + (c & 1) * 648;
        float* nxt = tiles + ((c + 1) & 1) * 648;

        // stage c+1 data (readers of nxt finished at iter c-1, synced)
        if (c < 127) {
            #pragma unroll
            for (int s = 0; s < 3; ++s) {
                int i = t + s * 256;
                if (i < 648) nxt[i] = rA[s];
            }
        }
        // issue loads for c+2 (latency hidden behind this iteration)
        if (c < 126) k2_prefetch(b, c + 2, y0, x0, t, rN);

        const float* wd1 = sdw + c * 9;
        const float* wd2 = sdw + (c + 128) * 9;
        float d1 = 0.f, d2 = 0.f;
        #pragma unroll
        for (int i = 0; i < 3; ++i)
            #pragma unroll
            for (int j = 0; j < 3; ++j) {
                d1 = fmaf(cur[(yl + i) * 18 + xl + j],       wd1[i * 3 + j], d1);
                d2 = fmaf(cur[324 + (yl + i) * 18 + xl + j], wd2[i * 3 + j], d2);
            }
        // exact GELU gate
        float g = 0.5f * d1 * (1.f + erff(d1 * 0.70710678118654752f)) * d2;
        unsigned long long gg = pk2(g, g);
        const unsigned long long* wrow =
            reinterpret_cast<const unsigned long long*>(swo + c * 66);
        #pragma unroll
        for (int j = 0; j < 32; ++j)
            acc2[j] = ffma2(wrow[j], gg, acc2[j]);

        __syncthreads();
        rA[0] = rN[0]; rA[1] = rN[1]; rA[2] = rN[2];
    }

    // stage output (sout aliases swo/sdw/tiles — all dead now)
    #pragma unroll
    for (int j = 0; j < 32; ++j) {
        float lo, hi;
        upk2(acc2[j], lo, hi);
        sout[t * 65 + 2 * j]     = lo;
        sout[t * 65 + 2 * j + 1] = hi;
    }
    __syncthreads();
    for (int k = 0; k < 64; ++k) {
        int e  = t + k * 256;
        int o  = e >> 8, px = e & 255;
        int oy = px >> 4, ox = px & 15;
        out[((b * 64 + o) << 16) + (y0 + oy) * 256 + x0 + ox] = sout[px * 65 + o];
    }
}

// ---------------------------------------------------------------------------
// launch
// ---------------------------------------------------------------------------
extern "C" void kernel_launch(void* const* d_in, const int* in_sizes, int n_in,
                              void* d_out, int out_size) {
    const float* x     = (const float*)d_in[0];   // (4,64,256,256)
    const float* w_in  = (const float*)d_in[1];   // (256,64)
    const float* w_dw  = (const float*)d_in[2];   // (256,1,3,3)
    const float* filt  = (const float*)d_in[3];   // (256,1,1,8,5)
    const float* w_out = (const float*)d_in[4];   // (64,128)
    float* out = (float*)d_out;                   // (4,64,256,256)

    cudaFuncSetAttribute(k_proj_spec, cudaFuncAttributeMaxDynamicSharedMemorySize, K1_SMEM);
    cudaFuncSetAttribute(k_dw_out,    cudaFuncAttributeMaxDynamicSharedMemorySize, K2_SMEM);

    k_prep<<<1, 256>>>(filt);
    k_proj_spec<<<HB * 32 * 32, 256, K1_SMEM>>>(x, w_in);
    k_dw_out<<<dim3(16, 16, HB), 256, K2_SMEM>>>(w_dw, w_out, out);
}